// round 3
// baseline (speedup 1.0000x reference)
#include <cuda_runtime.h>
#include <cstdint>

#define BATCH   4096
#define NFIELDS 32
#define DIM     64
#define NPAIRS  496
#define BM      64   // batch rows per block

__device__ __forceinline__ uint32_t f2tf32(float f) {
    uint32_t r;
    asm("cvt.rna.tf32.f32 %0, %1;" : "=r"(r) : "f"(f));
    return r;
}

__global__ void __launch_bounds__(128)
bilinear_tf32_kernel(const float* __restrict__ x,
                     const float* __restrict__ W,
                     float* __restrict__ out) {
    // stride 68 floats: bank index of [r][d] = (4r + d) mod 32 -> conflict-free
    __shared__ float sXi[BM][DIM + 4];
    __shared__ float sW [DIM][DIM + 4];

    const int p = blockIdx.y;
    // decode pair index p -> (i, j), lexicographic combinations of range(32)
    int i = 0, rem = p, cnt = NFIELDS - 1;
    while (rem >= cnt) { rem -= cnt; --cnt; ++i; }
    const int j = i + 1 + rem;

    const int bbase = blockIdx.x * BM;
    const int tid = threadIdx.x;

    // ---- stage Xi tile [BM x 64] (1024 float4, 8 per thread) ----
    {
        const float* src = x + ((size_t)bbase * NFIELDS + i) * DIM;
        #pragma unroll
        for (int t = 0; t < 8; ++t) {
            int idx = tid + t * 128;
            int row = idx >> 4;
            int c4  = (idx & 15) << 2;
            float4 v = *reinterpret_cast<const float4*>(
                src + (size_t)row * (NFIELDS * DIM) + c4);
            *reinterpret_cast<float4*>(&sXi[row][c4]) = v;
        }
    }
    // ---- stage W[p] tile [64 x 64] ----
    {
        const float* src = W + (size_t)p * DIM * DIM;
        #pragma unroll
        for (int t = 0; t < 8; ++t) {
            int idx = tid + t * 128;
            int row = idx >> 4;
            int c4  = (idx & 15) << 2;
            float4 v = *reinterpret_cast<const float4*>(src + row * DIM + c4);
            *reinterpret_cast<float4*>(&sW[row][c4]) = v;
        }
    }
    __syncthreads();

    const int warp = tid >> 5;
    const int lane = tid & 31;
    const int g  = lane >> 2;   // group id 0..7
    const int tg = lane & 3;    // thread in group 0..3

    // accumulators: 8 n-tiles (8 cols each) x 4 regs -> 16 rows x 64 cols per warp
    float acc[8][4];
    #pragma unroll
    for (int nt = 0; nt < 8; ++nt) {
        acc[nt][0] = 0.f; acc[nt][1] = 0.f; acc[nt][2] = 0.f; acc[nt][3] = 0.f;
    }

    const int arow = warp * 16 + g;

    #pragma unroll
    for (int kk = 0; kk < 8; ++kk) {
        const int k0 = kk * 8;
        // A fragment (m16n8k8 tf32, row-major):
        uint32_t a0 = f2tf32(sXi[arow    ][k0 + tg    ]);
        uint32_t a1 = f2tf32(sXi[arow + 8][k0 + tg    ]);
        uint32_t a2 = f2tf32(sXi[arow    ][k0 + tg + 4]);
        uint32_t a3 = f2tf32(sXi[arow + 8][k0 + tg + 4]);
        #pragma unroll
        for (int nt = 0; nt < 8; ++nt) {
            // B fragment (col-major 8x8): thread holds B[k=tg][n=g], B[k=tg+4][n=g]
            // B[k][n] = W[o=n][d=k]
            uint32_t br0 = f2tf32(sW[nt * 8 + g][k0 + tg    ]);
            uint32_t br1 = f2tf32(sW[nt * 8 + g][k0 + tg + 4]);
            asm volatile(
                "mma.sync.aligned.m16n8k8.row.col.f32.tf32.tf32.f32 "
                "{%0,%1,%2,%3}, {%4,%5,%6,%7}, {%8,%9}, {%0,%1,%2,%3};"
                : "+f"(acc[nt][0]), "+f"(acc[nt][1]),
                  "+f"(acc[nt][2]), "+f"(acc[nt][3])
                : "r"(a0), "r"(a1), "r"(a2), "r"(a3), "r"(br0), "r"(br1));
        }
    }

    // ---- epilogue: out[b,p,o] = proj * x[b,j,o] ----
    const int row0 = bbase + warp * 16 + g;
    const int row1 = row0 + 8;
    #pragma unroll
    for (int nt = 0; nt < 8; ++nt) {
        const int col = nt * 8 + tg * 2;   // c0/c1 are (col, col+1)
        float2 xj0 = *reinterpret_cast<const float2*>(
            x + ((size_t)row0 * NFIELDS + j) * DIM + col);
        float2 xj1 = *reinterpret_cast<const float2*>(
            x + ((size_t)row1 * NFIELDS + j) * DIM + col);
        float2 o0 = make_float2(acc[nt][0] * xj0.x, acc[nt][1] * xj0.y);
        float2 o1 = make_float2(acc[nt][2] * xj1.x, acc[nt][3] * xj1.y);
        *reinterpret_cast<float2*>(
            out + ((size_t)row0 * NPAIRS + p) * DIM + col) = o0;
        *reinterpret_cast<float2*>(
            out + ((size_t)row1 * NPAIRS + p) * DIM + col) = o1;
    }
}

extern "C" void kernel_launch(void* const* d_in, const int* in_sizes, int n_in,
                              void* d_out, int out_size) {
    const float* x = (const float*)d_in[0];
    const float* W = (const float*)d_in[1];
    float* out = (float*)d_out;
    dim3 grid(BATCH / BM, NPAIRS);
    bilinear_tf32_kernel<<<grid, 128>>>(x, W, out);
}

// round 4
// speedup vs baseline: 1.0015x; 1.0015x over previous
#include <cuda_runtime.h>
#include <cstdint>

#define BATCH   4096
#define NFIELDS 32
#define DIM     64
#define NPAIRS  496
#define BM      64   // batch rows per block

__device__ __forceinline__ uint32_t f2tf32(float f) {
    uint32_t r;
    asm("cvt.rna.tf32.f32 %0, %1;" : "=r"(r) : "f"(f));
    return r;
}

__global__ void __launch_bounds__(128)
bilinear_tf32_kernel(const float* __restrict__ x,
                     const float* __restrict__ W,
                     float* __restrict__ out) {
    // stride 68 floats: bank index of [r][d] = (4r + d) mod 32 -> conflict-free
    __shared__ float sXi[BM][DIM + 4];
    __shared__ float sW [DIM][DIM + 4];

    const int p = blockIdx.y;
    // decode pair index p -> (i, j), lexicographic combinations of range(32)
    int i = 0, rem = p, cnt = NFIELDS - 1;
    while (rem >= cnt) { rem -= cnt; --cnt; ++i; }
    const int j = i + 1 + rem;

    const int bbase = blockIdx.x * BM;
    const int tid = threadIdx.x;

    // ---- stage Xi tile [BM x 64] (1024 float4, 8 per thread) ----
    {
        const float* src = x + ((size_t)bbase * NFIELDS + i) * DIM;
        #pragma unroll
        for (int t = 0; t < 8; ++t) {
            int idx = tid + t * 128;
            int row = idx >> 4;
            int c4  = (idx & 15) << 2;
            float4 v = *reinterpret_cast<const float4*>(
                src + (size_t)row * (NFIELDS * DIM) + c4);
            *reinterpret_cast<float4*>(&sXi[row][c4]) = v;
        }
    }
    // ---- stage W[p] tile [64 x 64] ----
    {
        const float* src = W + (size_t)p * DIM * DIM;
        #pragma unroll
        for (int t = 0; t < 8; ++t) {
            int idx = tid + t * 128;
            int row = idx >> 4;
            int c4  = (idx & 15) << 2;
            float4 v = *reinterpret_cast<const float4*>(src + row * DIM + c4);
            *reinterpret_cast<float4*>(&sW[row][c4]) = v;
        }
    }
    __syncthreads();

    const int warp = tid >> 5;
    const int lane = tid & 31;
    const int g  = lane >> 2;   // group id 0..7
    const int tg = lane & 3;    // thread in group 0..3

    // accumulators: 8 n-tiles (8 cols each) x 4 regs -> 16 rows x 64 cols per warp
    float acc[8][4];
    #pragma unroll
    for (int nt = 0; nt < 8; ++nt) {
        acc[nt][0] = 0.f; acc[nt][1] = 0.f; acc[nt][2] = 0.f; acc[nt][3] = 0.f;
    }

    const int arow = warp * 16 + g;

    #pragma unroll
    for (int kk = 0; kk < 8; ++kk) {
        const int k0 = kk * 8;
        // A fragment (m16n8k8 tf32, row-major):
        uint32_t a0 = f2tf32(sXi[arow    ][k0 + tg    ]);
        uint32_t a1 = f2tf32(sXi[arow + 8][k0 + tg    ]);
        uint32_t a2 = f2tf32(sXi[arow    ][k0 + tg + 4]);
        uint32_t a3 = f2tf32(sXi[arow + 8][k0 + tg + 4]);
        #pragma unroll
        for (int nt = 0; nt < 8; ++nt) {
            // B fragment (col-major 8x8): thread holds B[k=tg][n=g], B[k=tg+4][n=g]
            // B[k][n] = W[o=n][d=k]
            uint32_t br0 = f2tf32(sW[nt * 8 + g][k0 + tg    ]);
            uint32_t br1 = f2tf32(sW[nt * 8 + g][k0 + tg + 4]);
            asm volatile(
                "mma.sync.aligned.m16n8k8.row.col.f32.tf32.tf32.f32 "
                "{%0,%1,%2,%3}, {%4,%5,%6,%7}, {%8,%9}, {%0,%1,%2,%3};"
                : "+f"(acc[nt][0]), "+f"(acc[nt][1]),
                  "+f"(acc[nt][2]), "+f"(acc[nt][3])
                : "r"(a0), "r"(a1), "r"(a2), "r"(a3), "r"(br0), "r"(br1));
        }
    }

    // ---- epilogue: out[b,p,o] = proj * x[b,j,o] ----
    const int row0 = bbase + warp * 16 + g;
    const int row1 = row0 + 8;
    #pragma unroll
    for (int nt = 0; nt < 8; ++nt) {
        const int col = nt * 8 + tg * 2;   // c0/c1 are (col, col+1)
        float2 xj0 = *reinterpret_cast<const float2*>(
            x + ((size_t)row0 * NFIELDS + j) * DIM + col);
        float2 xj1 = *reinterpret_cast<const float2*>(
            x + ((size_t)row1 * NFIELDS + j) * DIM + col);
        float2 o0 = make_float2(acc[nt][0] * xj0.x, acc[nt][1] * xj0.y);
        float2 o1 = make_float2(acc[nt][2] * xj1.x, acc[nt][3] * xj1.y);
        *reinterpret_cast<float2*>(
            out + ((size_t)row0 * NPAIRS + p) * DIM + col) = o0;
        *reinterpret_cast<float2*>(
            out + ((size_t)row1 * NPAIRS + p) * DIM + col) = o1;
    }
}

extern "C" void kernel_launch(void* const* d_in, const int* in_sizes, int n_in,
                              void* d_out, int out_size) {
    const float* x = (const float*)d_in[0];
    const float* W = (const float*)d_in[1];
    float* out = (float*)d_out;
    dim3 grid(BATCH / BM, NPAIRS);
    bilinear_tf32_kernel<<<grid, 128>>>(x, W, out);
}